// round 14
// baseline (speedup 1.0000x reference)
#include <cuda_runtime.h>
#include <math.h>
#include <stdint.h>

#define B 32
#define TIN 512
#define TOUT 800
#define NMEL 80
#define ENC 512
#define ARNN 1024
#define DRNN 1024
#define PRE 256
#define ATT 128
#define LOCF 32
#define LOCK 31
#define NB 128
#define NT 512

typedef unsigned long long ull;

static __device__ float g_pren[(size_t)TOUT * PRE * B];    // [t][j][b]
static __device__ float g_pmemT[(size_t)B * ATT * TIN];    // [b][a][t]
static __device__ float g_ah[2][ARNN * B];                 // [h][b]
static __device__ float g_ahbm[2][B * ARNN];               // [b][h]
static __device__ float g_ac[ARNN * B];
static __device__ float g_dh[2][DRNN * B];
static __device__ float g_dhbm[2][B * DRNN];
static __device__ float g_dc[DRNN * B];
static __device__ float g_aw[B * TIN];
static __device__ float g_awc[B * TIN];
static __device__ float g_ctxpart[2][4][ENC * B];          // [par][quarter][d][b]
static __device__ float g_energy[B * TIN];

struct PadCnt { unsigned v; unsigned pad[31]; };
static __device__ PadCnt g_gcnt[8];
static __device__ __align__(128) unsigned g_root;
static __device__ __align__(128) volatile unsigned g_epoch;

__device__ __forceinline__ float sigf(float x) { return __fdividef(1.f, 1.f + __expf(-x)); }
__device__ __forceinline__ float tanha(float x) {
    float y; asm("tanh.approx.f32 %0, %1;" : "=f"(y) : "f"(x)); return y;
}
__device__ __forceinline__ float wsum(float v) {
#pragma unroll
    for (int o = 16; o > 0; o >>= 1) v += __shfl_xor_sync(0xffffffffu, v, o);
    return v;
}
__device__ __forceinline__ float wmax(float v) {
#pragma unroll
    for (int o = 16; o > 0; o >>= 1) v = fmaxf(v, __shfl_xor_sync(0xffffffffu, v, o));
    return v;
}
#define FMA2(d, a, b) asm("fma.rn.f32x2 %0, %1, %2, %0;" : "+l"(d) : "l"(a), "l"(b))

__device__ __forceinline__ void gbar() {
    __syncthreads();
    if (threadIdx.x == 0) {
        unsigned e = g_epoch;
        __threadfence();
        unsigned r = atomicAdd(&g_gcnt[blockIdx.x >> 4].v, 1);
        if ((r & 15u) == 15u) {
            unsigned rr = atomicAdd(&g_root, 1);
            if ((rr & 7u) == 7u) { __threadfence(); g_epoch = e + 1; }
        }
        while (g_epoch == e) __nanosleep(32);
        __threadfence();
    }
    __syncthreads();
}

struct SLstm {
    float xs[2][8][32][34];    // [buf][kslice][b][kk] (pad 34 keeps b64 aligned)
    float zsum[8][32][33];     // [kslice][rowlocal=hl*4+g][b]
};
struct SAtt {
    float ahs[ARNN];
    float pqs[ATT]; float vs[ATT];
    float cat0[158]; float cat1[158];
    float cwsT[62][LOCF];
    float lls[ATT * LOCF];
    float lfs[128][LOCF + 1];
    float ep[NT];
};
struct SSoft { float sw[TIN]; float red[16]; float sd[DRNN + ENC]; };
union Smem { SLstm l; SAtt a; SSoft s; };

__global__ void zero_kernel() {
    int i = blockIdx.x * blockDim.x + threadIdx.x;
    if (i < ARNN * B) {
        g_ah[0][i] = 0.f; g_ah[1][i] = 0.f; g_ahbm[0][i] = 0.f; g_ahbm[1][i] = 0.f; g_ac[i] = 0.f;
        g_dh[0][i] = 0.f; g_dh[1][i] = 0.f; g_dhbm[0][i] = 0.f; g_dhbm[1][i] = 0.f; g_dc[i] = 0.f;
    }
    if (i < B * TIN) { g_aw[i] = 0.f; g_awc[i] = 0.f; }
    if (i < 4 * ENC * B) { g_ctxpart[0][0][i] = 0.f; g_ctxpart[1][0][i] = 0.f; }
    if (i < 8) g_gcnt[i].v = 0;
    if (i == 0) { g_root = 0; g_epoch = 0; }
}

__global__ __launch_bounds__(256)
void prenet_kernel(const float* __restrict__ dec, const float* __restrict__ w1,
                   const float* __restrict__ w2) {
    int t = blockIdx.x >> 5, b = blockIdx.x & 31, tid = threadIdx.x;
    __shared__ float xm[NMEL];
    __shared__ float x1[PRE];
    if (tid < NMEL)
        xm[tid] = (t == 0) ? 0.f : dec[(size_t)b * NMEL * TOUT + (size_t)tid * TOUT + (t - 1)];
    __syncthreads();
    {
        const float* w = w1 + tid * NMEL;
        float s = 0.f;
#pragma unroll
        for (int m = 0; m < NMEL; ++m) s += xm[m] * w[m];
        x1[tid] = fmaxf(s, 0.f);
    }
    __syncthreads();
    {
        const float* w = w2 + tid * PRE;
        float s = 0.f;
#pragma unroll 8
        for (int k = 0; k < PRE; ++k) s += x1[k] * w[k];
        g_pren[((size_t)t * PRE + tid) * B + b] = fmaxf(s, 0.f);
    }
}

__global__ __launch_bounds__(128)
void pmem_kernel(const float* __restrict__ memory, const float* __restrict__ memw) {
    int b = blockIdx.x, tb = blockIdx.y * 16, a = threadIdx.x;
    __shared__ __align__(16) float xs[64][16];
    __shared__ float ws[128 * 65];
    float acc[16];
#pragma unroll
    for (int i = 0; i < 16; ++i) acc[i] = 0.f;
    for (int e0 = 0; e0 < ENC; e0 += 64) {
        __syncthreads();
#pragma unroll
        for (int i2 = 0; i2 < 8; ++i2) {
            int idx = a + i2 * 128, ee = idx & 63, tt = idx >> 6;
            xs[ee][tt] = memory[(size_t)b * TIN * ENC + (size_t)(tb + tt) * ENC + e0 + ee];
        }
#pragma unroll
        for (int i2 = 0; i2 < 64; ++i2) {
            int idx = a + i2 * 128, ee = idx & 63, aa = idx >> 6;
            ws[aa * 65 + ee] = memw[aa * ENC + e0 + ee];
        }
        __syncthreads();
#pragma unroll 4
        for (int ee = 0; ee < 64; ++ee) {
            float w = ws[a * 65 + ee];
            const float4* xr = (const float4*)&xs[ee][0];
            float4 v0 = xr[0], v1 = xr[1], v2 = xr[2], v3 = xr[3];
            acc[0] += w * v0.x; acc[1] += w * v0.y; acc[2] += w * v0.z; acc[3] += w * v0.w;
            acc[4] += w * v1.x; acc[5] += w * v1.y; acc[6] += w * v1.z; acc[7] += w * v1.w;
            acc[8] += w * v2.x; acc[9] += w * v2.y; acc[10] += w * v2.z; acc[11] += w * v2.w;
            acc[12] += w * v3.x; acc[13] += w * v3.y; acc[14] += w * v3.z; acc[15] += w * v3.w;
        }
    }
    float* o = g_pmemT + (size_t)b * ATT * TIN + (size_t)a * TIN + tb;
#pragma unroll
    for (int i = 0; i < 16; ++i) o[i] = acc[i];
}

// ---- LSTM: in-block split-K=8, thread = 4 gate-rows (one h) x 4 batches, f32x2 FMA ----
template <int WA, int WB>
__device__ void lstm_fused(const float* __restrict__ srcA, const float* __restrict__ srcB4,
                           const float* __restrict__ hprev,
                           const float* __restrict__ wih, const float* __restrict__ whh,
                           const float* __restrict__ bih, const float* __restrict__ bhh,
                           float* __restrict__ cst, float* __restrict__ hout,
                           float* __restrict__ houtbm, SLstm& s) {
    constexpr int KX = WA + WB;
    constexpr int KTOT = KX + 1024;
    constexpr int SLICE = KTOT / 8;
    constexpr int NCH = SLICE / 32;
    const int tid = threadIdx.x;
    const int ks = tid >> 6;              // 0..7
    const int rg = (tid >> 3) & 7;        // h-local 0..7
    const int bg = tid & 7;               // batch group
    const int h0 = blockIdx.x * 8;
    const int h = h0 + rg;
    const int kbase = ks * SLICE;
    const float* wir[4];
    const float* whr[4];
#pragma unroll
    for (int g = 0; g < 4; ++g) {
        int j = g * 1024 + h;
        wir[g] = wih + (size_t)j * KX;
        whr[g] = whh + (size_t)j * 1024;
    }
    ull acc[4][4];
#pragma unroll
    for (int g = 0; g < 4; ++g)
#pragma unroll
        for (int j = 0; j < 4; ++j) acc[g][j] = 0ull;
    // stage chunk 0: 8 slices x 32 k x 32 b
#pragma unroll
    for (int i = 0; i < 16; ++i) {
        int idx = tid + i * NT;
        int ksl = idx >> 10, kk = (idx >> 5) & 31, bb = idx & 31;
        int k = ksl * SLICE + kk;
        float v;
        if (k < WA) v = srcA[k * B + bb];
        else if (k < KX) {
            const float* p = srcB4 + (k - WA) * B + bb;
            v = p[0] + p[ENC * B] + p[2 * ENC * B] + p[3 * ENC * B];
        } else v = hprev[(k - KX) * B + bb];
        s.xs[0][ksl][bb][kk] = v;
    }
    __syncthreads();
    for (int c = 0; c < NCH; ++c) {
        float xr[16];
        if (c + 1 < NCH) {
#pragma unroll
            for (int i = 0; i < 16; ++i) {
                int idx = tid + i * NT;
                int ksl = idx >> 10, kk = (idx >> 5) & 31, bb = idx & 31;
                int k = ksl * SLICE + (c + 1) * 32 + kk;
                float v;
                if (k < WA) v = srcA[k * B + bb];
                else if (k < KX) {
                    const float* p = srcB4 + (k - WA) * B + bb;
                    v = p[0] + p[ENC * B] + p[2 * ENC * B] + p[3 * ENC * B];
                } else v = hprev[(k - KX) * B + bb];
                xr[i] = v;
            }
        }
        const int kc = kbase + c * 32;
        const bool ih = (kc < KX);
        const float* wb0 = ih ? (wir[0] + kc) : (whr[0] + kc - KX);
        const float* wb1 = ih ? (wir[1] + kc) : (whr[1] + kc - KX);
        const float* wb2 = ih ? (wir[2] + kc) : (whr[2] + kc - KX);
        const float* wb3 = ih ? (wir[3] + kc) : (whr[3] + kc - KX);
        const float (*xb)[34] = s.xs[c & 1][ks];
#pragma unroll
        for (int kk = 0; kk < 32; kk += 4) {
            ull xp0a = *(const ull*)&xb[bg * 4 + 0][kk];
            ull xp0b = *(const ull*)&xb[bg * 4 + 0][kk + 2];
            ull xp1a = *(const ull*)&xb[bg * 4 + 1][kk];
            ull xp1b = *(const ull*)&xb[bg * 4 + 1][kk + 2];
            ull xp2a = *(const ull*)&xb[bg * 4 + 2][kk];
            ull xp2b = *(const ull*)&xb[bg * 4 + 2][kk + 2];
            ull xp3a = *(const ull*)&xb[bg * 4 + 3][kk];
            ull xp3b = *(const ull*)&xb[bg * 4 + 3][kk + 2];
            ulonglong2 w0 = __ldg((const ulonglong2*)(wb0 + kk));
            ulonglong2 w1 = __ldg((const ulonglong2*)(wb1 + kk));
            ulonglong2 w2 = __ldg((const ulonglong2*)(wb2 + kk));
            ulonglong2 w3 = __ldg((const ulonglong2*)(wb3 + kk));
            FMA2(acc[0][0], w0.x, xp0a); FMA2(acc[0][0], w0.y, xp0b);
            FMA2(acc[0][1], w0.x, xp1a); FMA2(acc[0][1], w0.y, xp1b);
            FMA2(acc[0][2], w0.x, xp2a); FMA2(acc[0][2], w0.y, xp2b);
            FMA2(acc[0][3], w0.x, xp3a); FMA2(acc[0][3], w0.y, xp3b);
            FMA2(acc[1][0], w1.x, xp0a); FMA2(acc[1][0], w1.y, xp0b);
            FMA2(acc[1][1], w1.x, xp1a); FMA2(acc[1][1], w1.y, xp1b);
            FMA2(acc[1][2], w1.x, xp2a); FMA2(acc[1][2], w1.y, xp2b);
            FMA2(acc[1][3], w1.x, xp3a); FMA2(acc[1][3], w1.y, xp3b);
            FMA2(acc[2][0], w2.x, xp0a); FMA2(acc[2][0], w2.y, xp0b);
            FMA2(acc[2][1], w2.x, xp1a); FMA2(acc[2][1], w2.y, xp1b);
            FMA2(acc[2][2], w2.x, xp2a); FMA2(acc[2][2], w2.y, xp2b);
            FMA2(acc[2][3], w2.x, xp3a); FMA2(acc[2][3], w2.y, xp3b);
            FMA2(acc[3][0], w3.x, xp0a); FMA2(acc[3][0], w3.y, xp0b);
            FMA2(acc[3][1], w3.x, xp1a); FMA2(acc[3][1], w3.y, xp1b);
            FMA2(acc[3][2], w3.x, xp2a); FMA2(acc[3][2], w3.y, xp2b);
            FMA2(acc[3][3], w3.x, xp3a); FMA2(acc[3][3], w3.y, xp3b);
        }
        if (c + 1 < NCH) {
            __syncthreads();
#pragma unroll
            for (int i = 0; i < 16; ++i) {
                int idx = tid + i * NT;
                s.xs[(c + 1) & 1][idx >> 10][idx & 31][(idx >> 5) & 31] = xr[i];
            }
            __syncthreads();
        }
    }
#pragma unroll
    for (int g = 0; g < 4; ++g)
#pragma unroll
        for (int j = 0; j < 4; ++j) {
            float2 f = *(float2*)&acc[g][j];
            s.zsum[ks][rg * 4 + g][bg * 4 + j] = f.x + f.y;
        }
    __syncthreads();
    if (tid < 256) {
        const int bb = tid & 31, hl = tid >> 5;
        const int hh = h0 + hl;
        float z[4];
#pragma unroll
        for (int g = 0; g < 4; ++g) {
            float sv = bih[g * 1024 + hh] + bhh[g * 1024 + hh];
#pragma unroll
            for (int q = 0; q < 8; ++q) sv += s.zsum[q][hl * 4 + g][bb];
            z[g] = sv;
        }
        float cc = cst[hh * B + bb];
        float cn = sigf(z[1]) * cc + sigf(z[0]) * tanhf(z[2]);
        cst[hh * B + bb] = cn;
        float hv = sigf(z[3]) * tanhf(cn);
        hout[hh * B + bb] = hv;
        houtbm[bb * 1024 + hh] = hv;
    }
    __syncthreads();
}

__device__ void energy_phase(const float* __restrict__ qw, const float* __restrict__ convw,
                             const float* __restrict__ loclin, const float* __restrict__ vw,
                             const int* __restrict__ lens, int cur, SAtt& s) {
    const int b = blockIdx.x >> 2;
    const int tbase = (blockIdx.x & 3) * 128;
    const int tid = threadIdx.x, warp = tid >> 5, lane = tid & 31;
    if (tid < 256) ((float4*)s.ahs)[tid] = ((const float4*)&g_ahbm[cur][b * ARNN])[tid];
    for (int i = tid; i < 158; i += NT) {
        int tp = tbase - 15 + i;
        bool ok = (tp >= 0 && tp < TIN);
        s.cat0[i] = ok ? g_aw[b * TIN + tp] : 0.f;
        s.cat1[i] = ok ? g_awc[b * TIN + tp] : 0.f;
    }
    for (int i = tid; i < 62 * LOCF; i += NT) s.cwsT[i >> 5][i & 31] = convw[(i & 31) * 62 + (i >> 5)];
    for (int i = tid; i < ATT * LOCF; i += NT) s.lls[i] = loclin[i];
    if (tid < ATT) s.vs[tid] = vw[tid];
    __syncthreads();
#pragma unroll 1
    for (int r = 0; r < 8; ++r) {
        int a = warp * 8 + r;
        const float4* w = (const float4*)(qw + (size_t)a * ARNN);
        const float4* hv = (const float4*)s.ahs;
        float acc = 0.f;
#pragma unroll
        for (int i = 0; i < 8; ++i) {
            float4 wq = __ldg(&w[lane + i * 32]);
            float4 xq = hv[lane + i * 32];
            acc += wq.x * xq.x + wq.y * xq.y + wq.z * xq.z + wq.w * xq.w;
        }
        acc = wsum(acc);
        if (lane == 0) s.pqs[a] = acc;
    }
    {
        const int t = tid & 127, fq = tid >> 7;
        float lf[8];
#pragma unroll
        for (int i = 0; i < 8; ++i) lf[i] = 0.f;
#pragma unroll 2
        for (int kc = 0; kc < 62; ++kc) {
            float cv = (kc < 31) ? s.cat0[t + kc] : s.cat1[t + kc - 31];
            const float4* w = (const float4*)&s.cwsT[kc][fq * 8];
            float4 w0 = w[0], w1 = w[1];
            lf[0] += cv * w0.x; lf[1] += cv * w0.y; lf[2] += cv * w0.z; lf[3] += cv * w0.w;
            lf[4] += cv * w1.x; lf[5] += cv * w1.y; lf[6] += cv * w1.z; lf[7] += cv * w1.w;
        }
#pragma unroll
        for (int i = 0; i < 8; ++i) s.lfs[t][fq * 8 + i] = lf[i];
    }
    __syncthreads();
    {
        const int t = tid & 127, aq = tid >> 7;
        float lfr[32];
#pragma unroll
        for (int i = 0; i < 32; ++i) lfr[i] = s.lfs[t][i];
        const float* pm = g_pmemT + (size_t)b * ATT * TIN + tbase + t;
        float e = 0.f;
#pragma unroll 2
        for (int a = aq * 32; a < aq * 32 + 32; ++a) {
            float s0 = s.pqs[a] + __ldg(&pm[(size_t)a * TIN]);
            const float4* ll = (const float4*)&s.lls[a * LOCF];
#pragma unroll
            for (int i = 0; i < 8; ++i) {
                float4 lv = ll[i];
                s0 += lv.x * lfr[i * 4] + lv.y * lfr[i * 4 + 1] + lv.z * lfr[i * 4 + 2] + lv.w * lfr[i * 4 + 3];
            }
            e += s.vs[a] * tanha(s0);
        }
        s.ep[tid] = e;
    }
    __syncthreads();
    if (tid < 128) {
        int tp = tbase + tid;
        float e = s.ep[tid] + s.ep[tid + 128] + s.ep[tid + 256] + s.ep[tid + 384];
        if (tp >= lens[b]) e = -1e9f;
        g_energy[b * TIN + tp] = e;
    }
}

__device__ void softctx_phase(const float* __restrict__ memory, int t, int cur,
                              float* __restrict__ out_align, SSoft& s) {
    const int b = blockIdx.x >> 2;
    const int q = blockIdx.x & 3;
    const int t0 = q * 128;
    const int tid = threadIdx.x, warp = tid >> 5, lane = tid & 31;
    float e = g_energy[b * TIN + tid];
    float m = wmax(e);
    if (lane == 0) s.red[warp] = m;
    __syncthreads();
    if (tid < 32) {
        float mm = (lane < 16) ? s.red[lane] : -3.4e38f;
        mm = wmax(mm);
        if (lane == 0) s.red[0] = mm;
    }
    __syncthreads();
    m = s.red[0];
    float p = __expf(e - m);
    float ps = wsum(p);
    __syncthreads();
    if (lane == 0) s.red[warp] = ps;
    __syncthreads();
    if (tid < 32) {
        float ss = (lane < 16) ? s.red[lane] : 0.f;
        ss = wsum(ss);
        if (lane == 0) s.red[0] = ss;
    }
    __syncthreads();
    float aw = p * __fdividef(1.f, s.red[0]);
    s.sw[tid] = aw;
    if (tid >= t0 && tid < t0 + 128) {
        g_aw[b * TIN + tid] = aw;
        g_awc[b * TIN + tid] += aw;
        out_align[((size_t)b * TOUT + t) * TIN + tid] = aw;
    }
    __syncthreads();
    const float* mb = memory + (size_t)b * TIN * ENC + (size_t)t0 * ENC + tid;
    float acc = 0.f;
#pragma unroll 4
    for (int tt = 0; tt < 128; ++tt)
        acc += s.sw[t0 + tt] * __ldg(&mb[(size_t)tt * ENC]);
    g_ctxpart[cur][q][tid * B + b] = acc;
}

__device__ void proj_phase(const float* __restrict__ pw, const float* __restrict__ pb,
                           const float* __restrict__ gw, const float* __restrict__ gb,
                           int tp, int b, float* __restrict__ out_mel,
                           float* __restrict__ out_gate, SSoft& s) {
    const int par = tp & 1;
    const int tid = threadIdx.x, warp = tid >> 5, lane = tid & 31;
    __syncthreads();
    for (int i = tid; i < DRNN; i += NT) s.sd[i] = g_dhbm[par][b * DRNN + i];
    for (int i = tid; i < ENC; i += NT) {
        const float* pp = &g_ctxpart[par][0][i * B + b];
        s.sd[DRNN + i] = pp[0] + pp[ENC * B] + pp[2 * ENC * B] + pp[3 * ENC * B];
    }
    __syncthreads();
    for (int r = warp; r < NMEL + 1; r += 16) {
        const float4* w = (const float4*)((r < NMEL) ? (pw + (size_t)r * (DRNN + ENC)) : gw);
        const float4* x = (const float4*)s.sd;
        float acc = 0.f;
#pragma unroll
        for (int i = 0; i < 12; ++i) {
            float4 wq = __ldg(&w[lane + i * 32]);
            float4 xq = x[lane + i * 32];
            acc += wq.x * xq.x + wq.y * xq.y + wq.z * xq.z + wq.w * xq.w;
        }
        acc = wsum(acc);
        if (lane == 0) {
            if (r < NMEL) out_mel[(size_t)b * NMEL * TOUT + (size_t)r * TOUT + tp] = acc + pb[r];
            else out_gate[(size_t)b * TOUT + tp] = acc + gb[0];
        }
    }
}

__global__ __launch_bounds__(NT, 1)
void persist_kernel(const float* __restrict__ memory,
                    const float* __restrict__ awih, const float* __restrict__ awhh,
                    const float* __restrict__ abih, const float* __restrict__ abhh,
                    const float* __restrict__ qw, const float* __restrict__ vw,
                    const float* __restrict__ convw, const float* __restrict__ loclin,
                    const float* __restrict__ dwih, const float* __restrict__ dwhh,
                    const float* __restrict__ dbih, const float* __restrict__ dbhh,
                    const float* __restrict__ pw, const float* __restrict__ pb,
                    const float* __restrict__ gw, const float* __restrict__ gb,
                    const int* __restrict__ lens,
                    float* __restrict__ out_mel, float* __restrict__ out_gate,
                    float* __restrict__ out_align) {
    extern __shared__ __align__(16) char smraw[];
    Smem& sm = *reinterpret_cast<Smem*>(smraw);
    for (int t = 0; t < TOUT; ++t) {
        const int cur = t & 1, prev = cur ^ 1;
        lstm_fused<PRE, ENC>(g_pren + (size_t)t * PRE * B, &g_ctxpart[prev][0][0],
                             &g_ah[prev][0], awih, awhh, abih, abhh,
                             g_ac, &g_ah[cur][0], &g_ahbm[cur][0], sm.l);
        gbar();
        energy_phase(qw, convw, loclin, vw, lens, cur, sm.a);
        gbar();
        softctx_phase(memory, t, cur, out_align, sm.s);
        if ((blockIdx.x & 3) == 3 && t > 0)
            proj_phase(pw, pb, gw, gb, t - 1, blockIdx.x >> 2, out_mel, out_gate, sm.s);
        gbar();
        lstm_fused<ARNN, ENC>(&g_ah[cur][0], &g_ctxpart[cur][0][0],
                              &g_dh[prev][0], dwih, dwhh, dbih, dbhh,
                              g_dc, &g_dh[cur][0], &g_dhbm[cur][0], sm.l);
        gbar();
    }
    if (blockIdx.x < 32)
        proj_phase(pw, pb, gw, gb, TOUT - 1, blockIdx.x, out_mel, out_gate, sm.s);
}

extern "C" void kernel_launch(void* const* d_in, const int* in_sizes, int n_in,
                              void* d_out, int out_size) {
    const float* memory = (const float*)d_in[0];
    const float* dec    = (const float*)d_in[1];
    const float* w1     = (const float*)d_in[2];
    const float* w2     = (const float*)d_in[3];
    const float* awih   = (const float*)d_in[4];
    const float* awhh   = (const float*)d_in[5];
    const float* abih   = (const float*)d_in[6];
    const float* abhh   = (const float*)d_in[7];
    const float* qw     = (const float*)d_in[8];
    const float* memw   = (const float*)d_in[9];
    const float* vw     = (const float*)d_in[10];
    const float* convw  = (const float*)d_in[11];
    const float* loclin = (const float*)d_in[12];
    const float* dwih   = (const float*)d_in[13];
    const float* dwhh   = (const float*)d_in[14];
    const float* dbih   = (const float*)d_in[15];
    const float* dbhh   = (const float*)d_in[16];
    const float* pw     = (const float*)d_in[17];
    const float* pb     = (const float*)d_in[18];
    const float* gw     = (const float*)d_in[19];
    const float* gb     = (const float*)d_in[20];
    const int*   lens   = (const int*)d_in[21];

    float* out_mel = (float*)d_out;
    float* out_gate = out_mel + (size_t)B * NMEL * TOUT;
    float* out_align = out_gate + (size_t)B * TOUT;

    cudaFuncSetAttribute(persist_kernel, cudaFuncAttributeMaxDynamicSharedMemorySize,
                         (int)sizeof(Smem));

    zero_kernel<<<(4 * ENC * B + 255) / 256, 256>>>();
    prenet_kernel<<<TOUT * B, 256>>>(dec, w1, w2);
    pmem_kernel<<<dim3(B, TIN / 16), 128>>>(memory, memw);
    persist_kernel<<<NB, NT, sizeof(Smem)>>>(memory, awih, awhh, abih, abhh, qw, vw,
                                             convw, loclin, dwih, dwhh, dbih, dbhh,
                                             pw, pb, gw, gb, lens,
                                             out_mel, out_gate, out_align);
}

// round 15
// speedup vs baseline: 1.1034x; 1.1034x over previous
#include <cuda_runtime.h>
#include <math.h>
#include <stdint.h>

#define B 32
#define TIN 512
#define TOUT 800
#define NMEL 80
#define ENC 512
#define ARNN 1024
#define DRNN 1024
#define PRE 256
#define ATT 128
#define LOCF 32
#define LOCK 31
#define NB 128
#define NT 512

static __device__ float g_pren[(size_t)TOUT * PRE * B];    // [t][j][b]
static __device__ float g_pmemT[(size_t)B * ATT * TIN];    // [b][a][t]
static __device__ float g_ah[2][ARNN * B];                 // [h][b]
static __device__ float g_ahbm[2][B * ARNN];               // [b][h]
static __device__ float g_ac[ARNN * B];
static __device__ float g_dh[2][DRNN * B];
static __device__ float g_dhbm[2][B * DRNN];
static __device__ float g_dc[DRNN * B];
static __device__ float g_aw[B * TIN];
static __device__ float g_awc[B * TIN];
static __device__ float g_ctx[2][ENC * B];                 // [par][d][b]  (final)
static __device__ float g_ctxbm[2][B * ENC];               // [par][b][d]  (final)
static __device__ float g_energy[B * TIN];

struct PadCnt { unsigned v; unsigned pad[31]; };
static __device__ PadCnt g_gcnt[8];
static __device__ __align__(128) unsigned g_root;
static __device__ __align__(128) volatile unsigned g_epoch;

__device__ __forceinline__ float sigf(float x) { return __fdividef(1.f, 1.f + __expf(-x)); }
__device__ __forceinline__ float tanha(float x) {
    float y; asm("tanh.approx.f32 %0, %1;" : "=f"(y) : "f"(x)); return y;
}
__device__ __forceinline__ float wsum(float v) {
#pragma unroll
    for (int o = 16; o > 0; o >>= 1) v += __shfl_xor_sync(0xffffffffu, v, o);
    return v;
}
__device__ __forceinline__ float wmax(float v) {
#pragma unroll
    for (int o = 16; o > 0; o >>= 1) v = fmaxf(v, __shfl_xor_sync(0xffffffffu, v, o));
    return v;
}

__device__ __forceinline__ void gbar() {
    __syncthreads();
    if (threadIdx.x == 0) {
        unsigned e = g_epoch;
        __threadfence();
        unsigned r = atomicAdd(&g_gcnt[blockIdx.x >> 4].v, 1);
        if ((r & 15u) == 15u) {
            unsigned rr = atomicAdd(&g_root, 1);
            if ((rr & 7u) == 7u) { __threadfence(); g_epoch = e + 1; }
        }
        while (g_epoch == e) __nanosleep(32);
        __threadfence();
    }
    __syncthreads();
}

struct SLstm {
    float xs[2][4][64][B];       // [buf][kslice][kk][b]
    float zsp[4][32][B];         // [kslice][rowlocal][b]
};
struct SAtt {
    float ahs[ARNN];
    float pqs[ATT]; float vs[ATT];
    float cat0[158]; float cat1[158];
    float cwsT[62][LOCF];
    float lls[ATT * LOCF];
    float lfs[128][LOCF + 1];
    float ep[NT];
};
struct SSoft { float sw[TIN]; float red[16]; float sd[DRNN + ENC]; };
union Smem { SLstm l; SAtt a; SSoft s; };

__global__ void zero_kernel() {
    int i = blockIdx.x * blockDim.x + threadIdx.x;
    if (i < ARNN * B) {
        g_ah[0][i] = 0.f; g_ah[1][i] = 0.f; g_ahbm[0][i] = 0.f; g_ahbm[1][i] = 0.f; g_ac[i] = 0.f;
        g_dh[0][i] = 0.f; g_dh[1][i] = 0.f; g_dhbm[0][i] = 0.f; g_dhbm[1][i] = 0.f; g_dc[i] = 0.f;
    }
    if (i < B * TIN) { g_aw[i] = 0.f; g_awc[i] = 0.f; }
    if (i < ENC * B) { g_ctx[0][i] = 0.f; g_ctx[1][i] = 0.f; g_ctxbm[0][i] = 0.f; g_ctxbm[1][i] = 0.f; }
    if (i < 8) g_gcnt[i].v = 0;
    if (i == 0) { g_root = 0; g_epoch = 0; }
}

__global__ __launch_bounds__(256)
void prenet_kernel(const float* __restrict__ dec, const float* __restrict__ w1,
                   const float* __restrict__ w2) {
    int t = blockIdx.x >> 5, b = blockIdx.x & 31, tid = threadIdx.x;
    __shared__ float xm[NMEL];
    __shared__ float x1[PRE];
    if (tid < NMEL)
        xm[tid] = (t == 0) ? 0.f : dec[(size_t)b * NMEL * TOUT + (size_t)tid * TOUT + (t - 1)];
    __syncthreads();
    {
        const float* w = w1 + tid * NMEL;
        float s = 0.f;
#pragma unroll
        for (int m = 0; m < NMEL; ++m) s += xm[m] * w[m];
        x1[tid] = fmaxf(s, 0.f);
    }
    __syncthreads();
    {
        const float* w = w2 + tid * PRE;
        float s = 0.f;
#pragma unroll 8
        for (int k = 0; k < PRE; ++k) s += x1[k] * w[k];
        g_pren[((size_t)t * PRE + tid) * B + b] = fmaxf(s, 0.f);
    }
}

__global__ __launch_bounds__(128)
void pmem_kernel(const float* __restrict__ memory, const float* __restrict__ memw) {
    int b = blockIdx.x, tb = blockIdx.y * 16, a = threadIdx.x;
    __shared__ __align__(16) float xs[64][16];
    __shared__ float ws[128 * 65];
    float acc[16];
#pragma unroll
    for (int i = 0; i < 16; ++i) acc[i] = 0.f;
    for (int e0 = 0; e0 < ENC; e0 += 64) {
        __syncthreads();
#pragma unroll
        for (int i2 = 0; i2 < 8; ++i2) {
            int idx = a + i2 * 128, ee = idx & 63, tt = idx >> 6;
            xs[ee][tt] = memory[(size_t)b * TIN * ENC + (size_t)(tb + tt) * ENC + e0 + ee];
        }
#pragma unroll
        for (int i2 = 0; i2 < 64; ++i2) {
            int idx = a + i2 * 128, ee = idx & 63, aa = idx >> 6;
            ws[aa * 65 + ee] = memw[aa * ENC + e0 + ee];
        }
        __syncthreads();
#pragma unroll 4
        for (int ee = 0; ee < 64; ++ee) {
            float w = ws[a * 65 + ee];
            const float4* xr = (const float4*)&xs[ee][0];
            float4 v0 = xr[0], v1 = xr[1], v2 = xr[2], v3 = xr[3];
            acc[0] += w * v0.x; acc[1] += w * v0.y; acc[2] += w * v0.z; acc[3] += w * v0.w;
            acc[4] += w * v1.x; acc[5] += w * v1.y; acc[6] += w * v1.z; acc[7] += w * v1.w;
            acc[8] += w * v2.x; acc[9] += w * v2.y; acc[10] += w * v2.z; acc[11] += w * v2.w;
            acc[12] += w * v3.x; acc[13] += w * v3.y; acc[14] += w * v3.z; acc[15] += w * v3.w;
        }
    }
    float* o = g_pmemT + (size_t)b * ATT * TIN + (size_t)a * TIN + tb;
#pragma unroll
    for (int i = 0; i < 16; ++i) o[i] = acc[i];
}

// ---- r7 LSTM engine, ctx now a single final buffer ----
template <int WA, int WB>
__device__ void lstm_fused(const float* __restrict__ srcA, const float* __restrict__ srcB,
                           const float* __restrict__ hprev,
                           const float* __restrict__ wih, const float* __restrict__ whh,
                           const float* __restrict__ bih, const float* __restrict__ bhh,
                           float* __restrict__ cst, float* __restrict__ hout,
                           float* __restrict__ hbm, SLstm& s) {
    constexpr int KX = WA + WB;
    constexpr int KTOT = KX + 1024;
    constexpr int SLICE = KTOT / 4;
    constexpr int NR = SLICE / 64;
    const int tid = threadIdx.x;
    const int ks = tid >> 7;
    const int sub = tid & 127;
    const int rg = sub >> 3;
    const int bg = sub & 7;
    const int g = rg >> 2, p = rg & 3;
    const int h0 = blockIdx.x * 8;
    const int j0 = g * 1024 + h0 + p * 2;
    const int kbase = ks * SLICE;
    const float* wihr = wih + (size_t)j0 * KX;
    const float* whhr = whh + (size_t)j0 * 1024;
    float a0[4] = {0, 0, 0, 0}, a1[4] = {0, 0, 0, 0};
#pragma unroll
    for (int i = 0; i < 16; ++i) {
        int idx = tid + i * NT;
        int ksl = idx >> 11, kk = (idx >> 5) & 63, bb = idx & 31;
        int k = ksl * SLICE + kk;
        float v;
        if (k < WA) v = srcA[k * B + bb];
        else if (k < KX) v = srcB[(k - WA) * B + bb];
        else v = hprev[(k - KX) * B + bb];
        s.xs[0][ksl][kk][bb] = v;
    }
    __syncthreads();
    for (int c = 0; c < NR; ++c) {
        const int k0 = kbase + c * 64;
        const bool ih = (k0 < KX);
        const float* w0 = ih ? (wihr + k0) : (whhr + (k0 - KX));
        const float* w1 = w0 + (ih ? KX : 1024);
        float xr[16];
        if (c + 1 < NR) {
#pragma unroll
            for (int i = 0; i < 16; ++i) {
                int idx = tid + i * NT;
                int ksl = idx >> 11, kk = (idx >> 5) & 63, bb = idx & 31;
                int k = ksl * SLICE + (c + 1) * 64 + kk;
                float v;
                if (k < WA) v = srcA[k * B + bb];
                else if (k < KX) v = srcB[(k - WA) * B + bb];
                else v = hprev[(k - KX) * B + bb];
                xr[i] = v;
            }
        }
        const float (*xb)[B] = s.xs[c & 1][ks];
#pragma unroll 4
        for (int q = 0; q < 16; ++q) {
            float4 wa = __ldg((const float4*)w0 + q);
            float4 wb = __ldg((const float4*)w1 + q);
            float4 x0 = *(const float4*)&xb[q * 4 + 0][bg * 4];
            float4 x1 = *(const float4*)&xb[q * 4 + 1][bg * 4];
            float4 x2 = *(const float4*)&xb[q * 4 + 2][bg * 4];
            float4 x3 = *(const float4*)&xb[q * 4 + 3][bg * 4];
            a0[0] += wa.x * x0.x; a0[1] += wa.x * x0.y; a0[2] += wa.x * x0.z; a0[3] += wa.x * x0.w;
            a1[0] += wb.x * x0.x; a1[1] += wb.x * x0.y; a1[2] += wb.x * x0.z; a1[3] += wb.x * x0.w;
            a0[0] += wa.y * x1.x; a0[1] += wa.y * x1.y; a0[2] += wa.y * x1.z; a0[3] += wa.y * x1.w;
            a1[0] += wb.y * x1.x; a1[1] += wb.y * x1.y; a1[2] += wb.y * x1.z; a1[3] += wb.y * x1.w;
            a0[0] += wa.z * x2.x; a0[1] += wa.z * x2.y; a0[2] += wa.z * x2.z; a0[3] += wa.z * x2.w;
            a1[0] += wb.z * x2.x; a1[1] += wb.z * x2.y; a1[2] += wb.z * x2.z; a1[3] += wb.z * x2.w;
            a0[0] += wa.w * x3.x; a0[1] += wa.w * x3.y; a0[2] += wa.w * x3.z; a0[3] += wa.w * x3.w;
            a1[0] += wb.w * x3.x; a1[1] += wb.w * x3.y; a1[2] += wb.w * x3.z; a1[3] += wb.w * x3.w;
        }
        if (c + 1 < NR) {
#pragma unroll
            for (int i = 0; i < 16; ++i) {
                int idx = tid + i * NT;
                s.xs[(c + 1) & 1][idx >> 11][(idx >> 5) & 63][idx & 31] = xr[i];
            }
        }
        __syncthreads();
    }
    {
        const int rl0 = g * 8 + p * 2;
        *(float4*)&s.zsp[ks][rl0][bg * 4] = make_float4(a0[0], a0[1], a0[2], a0[3]);
        *(float4*)&s.zsp[ks][rl0 + 1][bg * 4] = make_float4(a1[0], a1[1], a1[2], a1[3]);
    }
    __syncthreads();
    if (tid < 256) {
        const int bb = tid & 31, hl = tid >> 5;
        const int h = h0 + hl;
        float z[4];
#pragma unroll
        for (int gg = 0; gg < 4; ++gg) {
            const int j = gg * 1024 + h;
            float sv = bih[j] + bhh[j];
#pragma unroll
            for (int q = 0; q < 4; ++q) sv += s.zsp[q][gg * 8 + hl][bb];
            z[gg] = sv;
        }
        float c = cst[h * B + bb];
        float cn = sigf(z[1]) * c + sigf(z[0]) * tanhf(z[2]);
        cst[h * B + bb] = cn;
        float hv = sigf(z[3]) * tanhf(cn);
        hout[h * B + bb] = hv;
        hbm[bb * 1024 + h] = hv;
    }
    __syncthreads();
}

__device__ void energy_phase(const float* __restrict__ qw, const float* __restrict__ convw,
                             const float* __restrict__ loclin, const float* __restrict__ vw,
                             const int* __restrict__ lens, int cur, SAtt& s) {
    const int b = blockIdx.x >> 2;
    const int tbase = (blockIdx.x & 3) * 128;
    const int tid = threadIdx.x, warp = tid >> 5, lane = tid & 31;
    if (tid < 256) ((float4*)s.ahs)[tid] = ((const float4*)&g_ahbm[cur][b * ARNN])[tid];
    for (int i = tid; i < 158; i += NT) {
        int tp = tbase - 15 + i;
        bool ok = (tp >= 0 && tp < TIN);
        s.cat0[i] = ok ? g_aw[b * TIN + tp] : 0.f;
        s.cat1[i] = ok ? g_awc[b * TIN + tp] : 0.f;
    }
    for (int i = tid; i < 62 * LOCF; i += NT) s.cwsT[i >> 5][i & 31] = convw[(i & 31) * 62 + (i >> 5)];
    for (int i = tid; i < ATT * LOCF; i += NT) s.lls[i] = loclin[i];
    if (tid < ATT) s.vs[tid] = vw[tid];
    __syncthreads();
#pragma unroll 1
    for (int r = 0; r < 8; ++r) {
        int a = warp * 8 + r;
        const float4* w = (const float4*)(qw + (size_t)a * ARNN);
        const float4* hv = (const float4*)s.ahs;
        float acc = 0.f;
#pragma unroll
        for (int i = 0; i < 8; ++i) {
            float4 wq = __ldg(&w[lane + i * 32]);
            float4 xq = hv[lane + i * 32];
            acc += wq.x * xq.x + wq.y * xq.y + wq.z * xq.z + wq.w * xq.w;
        }
        acc = wsum(acc);
        if (lane == 0) s.pqs[a] = acc;
    }
    {
        const int t = tid & 127, fq = tid >> 7;
        float lf[8];
#pragma unroll
        for (int i = 0; i < 8; ++i) lf[i] = 0.f;
#pragma unroll 2
        for (int kc = 0; kc < 62; ++kc) {
            float cv = (kc < 31) ? s.cat0[t + kc] : s.cat1[t + kc - 31];
            const float4* w = (const float4*)&s.cwsT[kc][fq * 8];
            float4 w0 = w[0], w1 = w[1];
            lf[0] += cv * w0.x; lf[1] += cv * w0.y; lf[2] += cv * w0.z; lf[3] += cv * w0.w;
            lf[4] += cv * w1.x; lf[5] += cv * w1.y; lf[6] += cv * w1.z; lf[7] += cv * w1.w;
        }
#pragma unroll
        for (int i = 0; i < 8; ++i) s.lfs[t][fq * 8 + i] = lf[i];
    }
    __syncthreads();
    {
        const int t = tid & 127, aq = tid >> 7;
        float lfr[32];
#pragma unroll
        for (int i = 0; i < 32; ++i) lfr[i] = s.lfs[t][i];
        const float* pm = g_pmemT + (size_t)b * ATT * TIN + tbase + t;
        float e = 0.f;
#pragma unroll 2
        for (int a = aq * 32; a < aq * 32 + 32; ++a) {
            float s0 = s.pqs[a] + __ldg(&pm[(size_t)a * TIN]);
            const float4* ll = (const float4*)&s.lls[a * LOCF];
#pragma unroll
            for (int i = 0; i < 8; ++i) {
                float4 lv = ll[i];
                s0 += lv.x * lfr[i * 4] + lv.y * lfr[i * 4 + 1] + lv.z * lfr[i * 4 + 2] + lv.w * lfr[i * 4 + 3];
            }
            e += s.vs[a] * tanha(s0);
        }
        s.ep[tid] = e;
    }
    __syncthreads();
    if (tid < 128) {
        int tp = tbase + tid;
        float e = s.ep[tid] + s.ep[tid + 128] + s.ep[tid + 256] + s.ep[tid + 384];
        if (tp >= lens[b]) e = -1e9f;
        g_energy[b * TIN + tp] = e;
    }
}

// ---- softmax + FINAL ctx for d-slice [q*128, q*128+128) ----
__device__ void softctx_phase(const float* __restrict__ memory, int t, int cur,
                              float* __restrict__ out_align, SSoft& s) {
    const int b = blockIdx.x >> 2;
    const int q = blockIdx.x & 3;
    const int tid = threadIdx.x, warp = tid >> 5, lane = tid & 31;
    float e = g_energy[b * TIN + tid];
    float m = wmax(e);
    if (lane == 0) s.red[warp] = m;
    __syncthreads();
    if (tid < 32) {
        float mm = (lane < 16) ? s.red[lane] : -3.4e38f;
        mm = wmax(mm);
        if (lane == 0) s.red[0] = mm;
    }
    __syncthreads();
    m = s.red[0];
    float p = __expf(e - m);
    float ps = wsum(p);
    __syncthreads();
    if (lane == 0) s.red[warp] = ps;
    __syncthreads();
    if (tid < 32) {
        float ss = (lane < 16) ? s.red[lane] : 0.f;
        ss = wsum(ss);
        if (lane == 0) s.red[0] = ss;
    }
    __syncthreads();
    float aw = p * __fdividef(1.f, s.red[0]);
    s.sw[tid] = aw;
    if (q == 0) {
        g_aw[b * TIN + tid] = aw;
        g_awc[b * TIN + tid] += aw;
        out_align[((size_t)b * TOUT + t) * TIN + tid] = aw;
    }
    __syncthreads();
    // ctx for d = q*128 + dl, partial over t-quarter tq, then reduce 4 partials
    const int dl = tid & 127, tq = tid >> 7;
    const float* mb = memory + (size_t)b * TIN * ENC + (size_t)(tq * 128) * ENC + q * 128 + dl;
    float acc = 0.f;
#pragma unroll 4
    for (int tt = 0; tt < 128; ++tt)
        acc += s.sw[tq * 128 + tt] * __ldg(&mb[(size_t)tt * ENC]);
    s.sd[tq * 128 + dl] = acc;
    __syncthreads();
    if (tid < 128) {
        float c = s.sd[tid] + s.sd[128 + tid] + s.sd[256 + tid] + s.sd[384 + tid];
        int d = q * 128 + tid;
        g_ctx[cur][d * B + b] = c;
        g_ctxbm[cur][b * ENC + d] = c;
    }
    __syncthreads();
}

__device__ void proj_phase(const float* __restrict__ pw, const float* __restrict__ pb,
                           const float* __restrict__ gw, const float* __restrict__ gb,
                           int tp, int b, float* __restrict__ out_mel,
                           float* __restrict__ out_gate, SSoft& s) {
    const int par = tp & 1;
    const int tid = threadIdx.x, warp = tid >> 5, lane = tid & 31;
    __syncthreads();
    for (int i = tid; i < DRNN; i += NT) s.sd[i] = g_dhbm[par][b * DRNN + i];
    for (int i = tid; i < ENC; i += NT) s.sd[DRNN + i] = g_ctxbm[par][b * ENC + i];
    __syncthreads();
    for (int r = warp; r < NMEL + 1; r += 16) {
        const float4* w = (const float4*)((r < NMEL) ? (pw + (size_t)r * (DRNN + ENC)) : gw);
        const float4* x = (const float4*)s.sd;
        float acc = 0.f;
#pragma unroll
        for (int i = 0; i < 12; ++i) {
            float4 wq = __ldg(&w[lane + i * 32]);
            float4 xq = x[lane + i * 32];
            acc += wq.x * xq.x + wq.y * xq.y + wq.z * xq.z + wq.w * xq.w;
        }
        acc = wsum(acc);
        if (lane == 0) {
            if (r < NMEL) out_mel[(size_t)b * NMEL * TOUT + (size_t)r * TOUT + tp] = acc + pb[r];
            else out_gate[(size_t)b * TOUT + tp] = acc + gb[0];
        }
    }
}

__global__ __launch_bounds__(NT, 1)
void persist_kernel(const float* __restrict__ memory,
                    const float* __restrict__ awih, const float* __restrict__ awhh,
                    const float* __restrict__ abih, const float* __restrict__ abhh,
                    const float* __restrict__ qw, const float* __restrict__ vw,
                    const float* __restrict__ convw, const float* __restrict__ loclin,
                    const float* __restrict__ dwih, const float* __restrict__ dwhh,
                    const float* __restrict__ dbih, const float* __restrict__ dbhh,
                    const float* __restrict__ pw, const float* __restrict__ pb,
                    const float* __restrict__ gw, const float* __restrict__ gb,
                    const int* __restrict__ lens,
                    float* __restrict__ out_mel, float* __restrict__ out_gate,
                    float* __restrict__ out_align) {
    extern __shared__ __align__(16) char smraw[];
    Smem& sm = *reinterpret_cast<Smem*>(smraw);
    for (int t = 0; t < TOUT; ++t) {
        const int cur = t & 1, prev = cur ^ 1;
        lstm_fused<PRE, ENC>(g_pren + (size_t)t * PRE * B, &g_ctx[prev][0], &g_ah[prev][0],
                             awih, awhh, abih, abhh, g_ac, &g_ah[cur][0], &g_ahbm[cur][0], sm.l);
        gbar();
        energy_phase(qw, convw, loclin, vw, lens, cur, sm.a);
        gbar();
        softctx_phase(memory, t, cur, out_align, sm.s);
        if ((blockIdx.x & 3) == 3 && t > 0)
            proj_phase(pw, pb, gw, gb, t - 1, blockIdx.x >> 2, out_mel, out_gate, sm.s);
        gbar();
        lstm_fused<ARNN, ENC>(&g_ah[cur][0], &g_ctx[cur][0], &g_dh[prev][0],
                              dwih, dwhh, dbih, dbhh, g_dc, &g_dh[cur][0], &g_dhbm[cur][0], sm.l);
        gbar();
    }
    if (blockIdx.x < 32)
        proj_phase(pw, pb, gw, gb, TOUT - 1, blockIdx.x, out_mel, out_gate, sm.s);
}

extern "C" void kernel_launch(void* const* d_in, const int* in_sizes, int n_in,
                              void* d_out, int out_size) {
    const float* memory = (const float*)d_in[0];
    const float* dec    = (const float*)d_in[1];
    const float* w1     = (const float*)d_in[2];
    const float* w2     = (const float*)d_in[3];
    const float* awih   = (const float*)d_in[4];
    const float* awhh   = (const float*)d_in[5];
    const float* abih   = (const float*)d_in[6];
    const float* abhh   = (const float*)d_in[7];
    const float* qw     = (const float*)d_in[8];
    const float* memw   = (const float*)d_in[9];
    const float* vw     = (const float*)d_in[10];
    const float* convw  = (const float*)d_in[11];
    const float* loclin = (const float*)d_in[12];
    const float* dwih   = (const float*)d_in[13];
    const float* dwhh   = (const float*)d_in[14];
    const float* dbih   = (const float*)d_in[15];
    const float* dbhh   = (const float*)d_in[16];
    const float* pw     = (const float*)d_in[17];
    const float* pb     = (const float*)d_in[18];
    const float* gw     = (const float*)d_in[19];
    const float* gb     = (const float*)d_in[20];
    const int*   lens   = (const int*)d_in[21];

    float* out_mel = (float*)d_out;
    float* out_gate = out_mel + (size_t)B * NMEL * TOUT;
    float* out_align = out_gate + (size_t)B * TOUT;

    cudaFuncSetAttribute(persist_kernel, cudaFuncAttributeMaxDynamicSharedMemorySize,
                         (int)sizeof(Smem));

    zero_kernel<<<(ARNN * B + 255) / 256, 256>>>();
    prenet_kernel<<<TOUT * B, 256>>>(dec, w1, w2);
    pmem_kernel<<<dim3(B, TIN / 16), 128>>>(memory, memw);
    persist_kernel<<<NB, NT, sizeof(Smem)>>>(memory, awih, awhh, abih, abhh, qw, vw,
                                             convw, loclin, dwih, dwhh, dbih, dbhh,
                                             pw, pb, gw, gb, lens,
                                             out_mel, out_gate, out_align);
}